// round 2
// baseline (speedup 1.0000x reference)
#include <cuda_runtime.h>
#include <cuda_bf16.h>

// ---------------------------------------------------------------------------
// SimpleGCNNet:  Y = P^2 * X * W^T + b
//   X: (B*N, F) = (2048, 2000) fp32   (contiguous flat view of (32,8,64,250))
//   P: dense 64x64 propagation matrix from gcn_norm(edges + self loops)
//   W: (128, 2000), b: (128,)  ->  Y: (32, 64, 128)
// Kernels:
//   1) build_p2: edges -> P -> P^2           (1 block; dtype-robust edge read)
//   2) gemm_xwT: Z = X @ W^T                 (f32x2 packed-FMA tiled GEMM)
//   3) apply_p2: Y[b] = P^2 @ Z[b] + bias    (1 block per batch)
// ---------------------------------------------------------------------------

#define NNODE 64
#define GM 2048          // B*N rows
#define GK 2000          // F = Kk*T
#define GH 128           // H
#define TM 16            // GEMM m-tile
#define KT 16            // GEMM k-tile
#define NT (GK / KT)     // 125 k-tiles
#define EPSW 1e-6f

__device__ float g_P2[NNODE * NNODE];
__device__ float g_Z[GM * GH];

// ---- packed fp32x2 helpers (Blackwell FFMA2 path) -------------------------
__device__ __forceinline__ unsigned long long pack2(float lo, float hi) {
    unsigned long long r;
    asm("mov.b64 %0, {%1, %2};" : "=l"(r) : "f"(lo), "f"(hi));
    return r;
}
__device__ __forceinline__ unsigned long long fma2(unsigned long long a,
                                                   unsigned long long b,
                                                   unsigned long long c) {
    unsigned long long d;
    asm("fma.rn.f32x2 %0, %1, %2, %3;" : "=l"(d) : "l"(a), "l"(b), "l"(c));
    return d;
}
__device__ __forceinline__ float2 unpack2(unsigned long long v) {
    float2 f;
    asm("mov.b64 {%0, %1}, %2;" : "=f"(f.x), "=f"(f.y) : "l"(v));
    return f;
}

// ---------------------------------------------------------------------------
// Kernel 1: build P (64x64) from edges, then P2 = P @ P. Single block.
// edge_index buffer is read as raw 32-bit words; the kernel detects whether
// the underlying dtype is int64 (odd words all zero) or int32.
// ---------------------------------------------------------------------------
__global__ __launch_bounds__(256) void build_p2_kernel(
    const int* __restrict__ eiw, const float* __restrict__ ew, int E) {
    __shared__ float P[NNODE * NNODE];
    __shared__ float deg[NNODE];
    __shared__ float dinv[NNODE];
    __shared__ int odd_nonzero;
    const int tid = threadIdx.x;

    for (int i = tid; i < NNODE * NNODE; i += 256) P[i] = 0.0f;
    if (tid < NNODE) deg[tid] = 1.0f;  // self-loop weight = 1.0
    if (tid == 0) odd_nonzero = 0;
    __syncthreads();

    // dtype detect: int64 little-endian values in [0,64) -> odd words == 0
    if (tid < 64) {
        if (eiw[2 * tid + 1] != 0) atomicOr(&odd_nonzero, 1);
    }
    __syncthreads();
    const bool is64 = (odd_nonzero == 0);
    const int stride = is64 ? 2 : 1;
    const int dst_base = is64 ? 2 * E : E;

    for (int e = tid; e < E; e += 256) {
        float w = ew[e];
        if (w <= 0.0f) w = EPSW;
        int d = eiw[dst_base + e * stride] & (NNODE - 1);
        atomicAdd(&deg[d], w);
    }
    __syncthreads();

    if (tid < NNODE) {
        float d = deg[tid];
        dinv[tid] = (d > 0.0f) ? rsqrtf(d) : 0.0f;
    }
    __syncthreads();

    for (int e = tid; e < E; e += 256) {
        float w = ew[e];
        if (w <= 0.0f) w = EPSW;
        int s = eiw[e * stride] & (NNODE - 1);
        int d = eiw[dst_base + e * stride] & (NNODE - 1);
        atomicAdd(&P[d * NNODE + s], dinv[s] * w * dinv[d]);
    }
    if (tid < NNODE) atomicAdd(&P[tid * NNODE + tid], dinv[tid] * dinv[tid]);
    __syncthreads();

    // P2 = P @ P (16 entries per thread)
    for (int i = tid; i < NNODE * NNODE; i += 256) {
        int r = i >> 6, c = i & 63;
        float acc = 0.0f;
#pragma unroll 16
        for (int m = 0; m < NNODE; m++) acc += P[r * NNODE + m] * P[m * NNODE + c];
        g_P2[i] = acc;
    }
}

// ---------------------------------------------------------------------------
// Kernel 2: Z = X @ W^T.  X:(2048,2000) W:(128,2000) -> Z:(2048,128)
// 128 blocks x 256 threads. Block tile: 16(m) x 128(h). Thread tile: 2m x 4h
// held as 4 f32x2 accumulators (pairs along h). Double-buffered SMEM,
// distance-2 register prefetch for both X and W.
// ---------------------------------------------------------------------------
__global__ __launch_bounds__(256) void gemm_xwT_kernel(
    const float* __restrict__ X, const float* __restrict__ W) {
    __shared__ __align__(8)  float Xs[2][KT][TM + 2];   // transposed [k][m], padded
    __shared__ __align__(16) float Ws[2][KT][GH];       // transposed [k][h]

    const int tid = threadIdx.x;
    const int tx = tid & 31, ty = tid >> 5;
    const int m_base = blockIdx.x * TM;
    const int h0 = tx * 4;
    const int mloc = ty * 2;

    // loader roles
    const int xm = tid >> 4, xk = tid & 15;             // X tile: 1 float/thread
    const float* xp = X + (size_t)(m_base + xm) * GK + xk;
    const int h_a = tid >> 2, kq = tid & 3;             // W tile: 2 float4/thread
    const int h_b = h_a + 64;
    const float* wpa = W + (size_t)h_a * GK + kq * 4;
    const float* wpb = W + (size_t)h_b * GK + kq * 4;
    const int kr = kq * 4;

    unsigned long long a00 = 0ull, a01 = 0ull, a10 = 0ull, a11 = 0ull;

    float xr[2];
    float4 wa[2], wb[2];

    // prologue: tile 0 straight into buf0, prefetch tiles 1 and 2 into regs
    {
        float x0 = xp[0];
        float4 va = *(const float4*)(wpa);
        float4 vb = *(const float4*)(wpb);
        Xs[0][xk][xm] = x0;
        Ws[0][kr + 0][h_a] = va.x; Ws[0][kr + 1][h_a] = va.y;
        Ws[0][kr + 2][h_a] = va.z; Ws[0][kr + 3][h_a] = va.w;
        Ws[0][kr + 0][h_b] = vb.x; Ws[0][kr + 1][h_b] = vb.y;
        Ws[0][kr + 2][h_b] = vb.z; Ws[0][kr + 3][h_b] = vb.w;
    }
    xr[1] = xp[1 * KT]; wa[1] = *(const float4*)(wpa + 1 * KT); wb[1] = *(const float4*)(wpb + 1 * KT);
    xr[0] = xp[2 * KT]; wa[0] = *(const float4*)(wpa + 2 * KT); wb[0] = *(const float4*)(wpb + 2 * KT);
    __syncthreads();

    for (int t = 0; t < NT; t++) {
        const int cur = t & 1;
        const int nb = cur ^ 1;

        // store tile t+1 (loaded 2 iters ago) into the other buffer
        if (t + 1 < NT) {
            Xs[nb][xk][xm] = xr[nb];
            float4 va = wa[nb], vb = wb[nb];
            Ws[nb][kr + 0][h_a] = va.x; Ws[nb][kr + 1][h_a] = va.y;
            Ws[nb][kr + 2][h_a] = va.z; Ws[nb][kr + 3][h_a] = va.w;
            Ws[nb][kr + 0][h_b] = vb.x; Ws[nb][kr + 1][h_b] = vb.y;
            Ws[nb][kr + 2][h_b] = vb.z; Ws[nb][kr + 3][h_b] = vb.w;
        }
        // issue loads for tile t+3 (consumed 2 iterations from now)
        if (t + 3 < NT) {
            const int off = (t + 3) * KT;
            xr[nb] = xp[off];
            wa[nb] = *(const float4*)(wpa + off);
            wb[nb] = *(const float4*)(wpb + off);
        }

        // compute on buf[cur]: per k -> LDS.64 + LDS.128 + 2 pack + 4 FFMA2
#pragma unroll
        for (int k = 0; k < KT; k++) {
            float2 xv = *(const float2*)&Xs[cur][k][mloc];
            unsigned long long dx0 = pack2(xv.x, xv.x);
            unsigned long long dx1 = pack2(xv.y, xv.y);
            ulonglong2 wv = *(const ulonglong2*)&Ws[cur][k][h0];
            a00 = fma2(dx0, wv.x, a00);
            a01 = fma2(dx0, wv.y, a01);
            a10 = fma2(dx1, wv.x, a10);
            a11 = fma2(dx1, wv.y, a11);
        }
        __syncthreads();
    }

    const int gm = m_base + mloc;
    float2 v00 = unpack2(a00), v01 = unpack2(a01);
    float2 v10 = unpack2(a10), v11 = unpack2(a11);
    *(float4*)&g_Z[(size_t)gm * GH + h0]       = make_float4(v00.x, v00.y, v01.x, v01.y);
    *(float4*)&g_Z[(size_t)(gm + 1) * GH + h0] = make_float4(v10.x, v10.y, v11.x, v11.y);
}

// ---------------------------------------------------------------------------
// Kernel 3: Y[b] = P2 @ Z[b] + bias.  One block per batch (32 blocks).
// Thread: one h-pair (f32x2) x 16 n-rows.
// ---------------------------------------------------------------------------
__global__ __launch_bounds__(256) void apply_p2_kernel(
    const float* __restrict__ bias, float* __restrict__ y) {
    __shared__ __align__(16) float Zs[NNODE * GH];     // 32 KB
    __shared__ float Ps[NNODE * NNODE];                // 16 KB
    const int b = blockIdx.x, tid = threadIdx.x;

    const float* zb = g_Z + (size_t)b * NNODE * GH;
    for (int i = tid; i < NNODE * GH; i += 256) Zs[i] = zb[i];
    for (int i = tid; i < NNODE * NNODE; i += 256) Ps[i] = g_P2[i];
    __syncthreads();

    const int hp = tid & 63;          // h pair: columns 2hp, 2hp+1
    const int n0 = (tid >> 6) * 16;   // 16 output rows per thread

    unsigned long long acc[16];
    float2 bv = *(const float2*)(bias + 2 * hp);
    unsigned long long bini = pack2(bv.x, bv.y);
#pragma unroll
    for (int i = 0; i < 16; i++) acc[i] = bini;

    for (int m = 0; m < NNODE; m++) {
        unsigned long long zp = *(const unsigned long long*)&Zs[m * GH + 2 * hp];
#pragma unroll
        for (int i = 0; i < 16; i++) {
            float p = Ps[(n0 + i) * NNODE + m];
            acc[i] = fma2(pack2(p, p), zp, acc[i]);
        }
    }

    float* yb = y + (size_t)b * NNODE * GH;
#pragma unroll
    for (int i = 0; i < 16; i++) {
        float2 v = unpack2(acc[i]);
        *(float2*)&yb[(n0 + i) * GH + 2 * hp] = v;
    }
}

// ---------------------------------------------------------------------------
extern "C" void kernel_launch(void* const* d_in, const int* in_sizes, int n_in,
                              void* d_out, int out_size) {
    const float* x    = (const float*)d_in[0];      // (32,8,64,250) fp32
    const int*   eiw  = (const int*)d_in[1];        // (2,E) int64 OR int32 (raw words)
    const float* ew   = (const float*)d_in[2];      // (E,) fp32
    const float* W    = (const float*)d_in[3];      // (128,2000) fp32
    const float* bias = (const float*)d_in[4];      // (128,) fp32
    float*       y    = (float*)d_out;              // (32,64,128) fp32

    const int E = in_sizes[1] / 2;                  // element count / 2 rows

    build_p2_kernel<<<1, 256>>>(eiw, ew, E);
    gemm_xwT_kernel<<<GM / TM, 256>>>(x, W);
    apply_p2_kernel<<<32, 256>>>(bias, y);
}

// round 3
// speedup vs baseline: 1.6800x; 1.6800x over previous
#include <cuda_runtime.h>
#include <cuda_bf16.h>

// ---------------------------------------------------------------------------
// SimpleGCNNet:  Y = P^2 * X * W^T + b
//   X: (2048, 2000) fp32, W: (128, 2000), b: (128,) -> Y: (32, 64, 128)
// Kernel A (grid 129): blocks 0..127 -> Z-partials = X @ W^T (K-split x2,
//                      32m x 128h tile, 4m x 4h/thread, f32x2 FFMA);
//                      block 128 -> build P, P2 (runs concurrently)
// Kernel B (grid 64):  Y[b] = P2 @ (Zp0+Zp1)[b] + bias
// ---------------------------------------------------------------------------

#define NNODE 64
#define GM 2048
#define GK 2000
#define GH 128
#define TM 32            // GEMM m-tile
#define KT 16            // GEMM k-tile
#define KSPLIT0 992      // k in [0,992) -> 62 tiles ; [992,2000) -> 63 tiles
#define EPSW 1e-6f

__device__ float g_P2[NNODE * NNODE];
__device__ float g_Zp[2][GM * GH];

// ---- packed fp32x2 helpers ------------------------------------------------
__device__ __forceinline__ unsigned long long pack2(float lo, float hi) {
    unsigned long long r;
    asm("mov.b64 %0, {%1, %2};" : "=l"(r) : "f"(lo), "f"(hi));
    return r;
}
__device__ __forceinline__ unsigned long long fma2(unsigned long long a,
                                                   unsigned long long b,
                                                   unsigned long long c) {
    unsigned long long d;
    asm("fma.rn.f32x2 %0, %1, %2, %3;" : "=l"(d) : "l"(a), "l"(b), "l"(c));
    return d;
}
__device__ __forceinline__ float2 unpack2(unsigned long long v) {
    float2 f;
    asm("mov.b64 {%0, %1}, %2;" : "=f"(f.x), "=f"(f.y) : "l"(v));
    return f;
}

// ---------------------------------------------------------------------------
// build P -> P2 (device function, executed by one block of the GEMM grid)
// ---------------------------------------------------------------------------
__device__ void build_p2_body(const int* __restrict__ eiw,
                              const float* __restrict__ ew, int E) {
    __shared__ float P[NNODE * NNODE];
    __shared__ float deg[NNODE];
    __shared__ float dinv[NNODE];
    __shared__ int odd_nonzero;
    const int tid = threadIdx.x;

    for (int i = tid; i < NNODE * NNODE; i += 256) P[i] = 0.0f;
    if (tid < NNODE) deg[tid] = 1.0f;  // self-loop weight 1.0
    if (tid == 0) odd_nonzero = 0;
    __syncthreads();

    // dtype detect: int64 little-endian values in [0,64) -> odd words == 0
    if (tid < 64) {
        if (eiw[2 * tid + 1] != 0) atomicOr(&odd_nonzero, 1);
    }
    __syncthreads();
    const bool is64 = (odd_nonzero == 0);
    const int stride = is64 ? 2 : 1;
    const int dst_base = is64 ? 2 * E : E;

    for (int e = tid; e < E; e += 256) {
        float w = ew[e];
        if (w <= 0.0f) w = EPSW;
        atomicAdd(&deg[eiw[dst_base + e * stride] & (NNODE - 1)], w);
    }
    __syncthreads();

    if (tid < NNODE) {
        float d = deg[tid];
        dinv[tid] = (d > 0.0f) ? rsqrtf(d) : 0.0f;
    }
    __syncthreads();

    for (int e = tid; e < E; e += 256) {
        float w = ew[e];
        if (w <= 0.0f) w = EPSW;
        int s = eiw[e * stride] & (NNODE - 1);
        int d = eiw[dst_base + e * stride] & (NNODE - 1);
        atomicAdd(&P[d * NNODE + s], dinv[s] * w * dinv[d]);
    }
    if (tid < NNODE) atomicAdd(&P[tid * NNODE + tid], dinv[tid] * dinv[tid]);
    __syncthreads();

    for (int i = tid; i < NNODE * NNODE; i += 256) {
        int r = i >> 6, c = i & 63;
        float acc = 0.0f;
#pragma unroll 16
        for (int m = 0; m < NNODE; m++) acc += P[r * NNODE + m] * P[m * NNODE + c];
        g_P2[i] = acc;
    }
}

// ---------------------------------------------------------------------------
// Kernel A: GEMM Z-partials + P2 build
//  blocks 0..127: m-tile = bid & 63 (32 rows), ks = bid >> 6 (k-split half)
//  256 threads; thread tile 4m x 4h; double-buffered smem, dist-2 prefetch.
// ---------------------------------------------------------------------------
__global__ __launch_bounds__(256) void gemm_build_kernel(
    const float* __restrict__ X, const float* __restrict__ W,
    const int* __restrict__ eiw, const float* __restrict__ ew, int E) {

    if (blockIdx.x == 128) { build_p2_body(eiw, ew, E); return; }

    __shared__ __align__(16) float Xs[2][KT][TM + 4];   // [k][m], stride 36
    __shared__ __align__(16) float Ws[2][KT][GH];       // [k][h]

    const int tid = threadIdx.x;
    const int ks = blockIdx.x >> 6;
    const int m_base = (blockIdx.x & 63) * TM;
    const int k0 = ks ? KSPLIT0 : 0;
    const int NTb = ks ? 63 : 62;

    // compute mapping: 4m x 4h per thread
    const int tx = tid & 31, ty = tid >> 5;
    const int h0 = tx * 4;        // 4 consecutive h
    const int mloc = ty * 4;      // 4 consecutive m

    // loader mapping
    const int xm = tid >> 3, xk = (tid & 7) * 2;        // X: 1 float2 / thread
    const float* xp = X + (size_t)(m_base + xm) * GK + k0 + xk;
    const int h_w = tid & 127, wk = (tid >> 7) * 8;     // W: 2 float4 / thread
    const float* wp = W + (size_t)h_w * GK + k0 + wk;

    unsigned long long acc[8];
#pragma unroll
    for (int i = 0; i < 8; i++) acc[i] = 0ull;

    float2 xr[2];
    float4 w4[2][2];

    // prologue: tile 0 -> smem buf0 ; tiles 1,2 -> regs
    {
        float2 x0 = *(const float2*)(xp);
        float4 va = *(const float4*)(wp);
        float4 vb = *(const float4*)(wp + 4);
        Xs[0][xk][xm] = x0.x; Xs[0][xk + 1][xm] = x0.y;
        Ws[0][wk + 0][h_w] = va.x; Ws[0][wk + 1][h_w] = va.y;
        Ws[0][wk + 2][h_w] = va.z; Ws[0][wk + 3][h_w] = va.w;
        Ws[0][wk + 4][h_w] = vb.x; Ws[0][wk + 5][h_w] = vb.y;
        Ws[0][wk + 6][h_w] = vb.z; Ws[0][wk + 7][h_w] = vb.w;
    }
    xr[1] = *(const float2*)(xp + KT);
    w4[1][0] = *(const float4*)(wp + KT);
    w4[1][1] = *(const float4*)(wp + KT + 4);
    xr[0] = *(const float2*)(xp + 2 * KT);
    w4[0][0] = *(const float4*)(wp + 2 * KT);
    w4[0][1] = *(const float4*)(wp + 2 * KT + 4);
    __syncthreads();

    for (int t = 0; t < NTb; t++) {
        const int cur = t & 1;
        const int nb = cur ^ 1;

        if (t + 1 < NTb) {   // store tile t+1 (prefetched 2 iters ago)
            Xs[nb][xk][xm] = xr[nb].x; Xs[nb][xk + 1][xm] = xr[nb].y;
            float4 va = w4[nb][0], vb = w4[nb][1];
            Ws[nb][wk + 0][h_w] = va.x; Ws[nb][wk + 1][h_w] = va.y;
            Ws[nb][wk + 2][h_w] = va.z; Ws[nb][wk + 3][h_w] = va.w;
            Ws[nb][wk + 4][h_w] = vb.x; Ws[nb][wk + 5][h_w] = vb.y;
            Ws[nb][wk + 6][h_w] = vb.z; Ws[nb][wk + 7][h_w] = vb.w;
        }
        if (t + 3 < NTb) {   // prefetch tile t+3
            const int off = (t + 3) * KT;
            xr[nb] = *(const float2*)(xp + off);
            w4[nb][0] = *(const float4*)(wp + off);
            w4[nb][1] = *(const float4*)(wp + off + 4);
        }

#pragma unroll
        for (int k = 0; k < KT; k++) {
            float4 xv = *(const float4*)&Xs[cur][k][mloc];       // broadcast
            ulonglong2 wv = *(const ulonglong2*)&Ws[cur][k][h0]; // 4h = 2 pairs
            unsigned long long p0 = pack2(xv.x, xv.x);
            unsigned long long p1 = pack2(xv.y, xv.y);
            unsigned long long p2 = pack2(xv.z, xv.z);
            unsigned long long p3 = pack2(xv.w, xv.w);
            acc[0] = fma2(p0, wv.x, acc[0]); acc[1] = fma2(p0, wv.y, acc[1]);
            acc[2] = fma2(p1, wv.x, acc[2]); acc[3] = fma2(p1, wv.y, acc[3]);
            acc[4] = fma2(p2, wv.x, acc[4]); acc[5] = fma2(p2, wv.y, acc[5]);
            acc[6] = fma2(p3, wv.x, acc[6]); acc[7] = fma2(p3, wv.y, acc[7]);
        }
        __syncthreads();
    }

    float* zp = g_Zp[ks];
#pragma unroll
    for (int r = 0; r < 4; r++) {
        float2 va = unpack2(acc[2 * r]), vb = unpack2(acc[2 * r + 1]);
        *(float4*)&zp[(size_t)(m_base + mloc + r) * GH + h0] =
            make_float4(va.x, va.y, vb.x, vb.y);
    }
}

// ---------------------------------------------------------------------------
// Kernel B: Y[b, nh:nh+32, :] = P2[nh:nh+32,:] @ (Zp0+Zp1)[b] + bias
// grid 64 = 32 batches x 2 node-halves; 256 threads.
// ---------------------------------------------------------------------------
__global__ __launch_bounds__(256) void apply_p2_kernel(
    const float* __restrict__ bias, float* __restrict__ y) {
    __shared__ __align__(16) float Zs[NNODE * GH];       // 32 KB
    __shared__ float Ps[32 * NNODE];                     // 8 KB
    const int b = blockIdx.x >> 1;
    const int nh = (blockIdx.x & 1) * 32;
    const int tid = threadIdx.x;

    const float* z0 = g_Zp[0] + (size_t)b * NNODE * GH;
    const float* z1 = g_Zp[1] + (size_t)b * NNODE * GH;
    for (int i = tid; i < NNODE * GH; i += 256) Zs[i] = z0[i] + z1[i];
    for (int i = tid; i < 32 * NNODE; i += 256) Ps[i] = g_P2[nh * NNODE + i];
    __syncthreads();

    const int hp = tid & 63;          // h pair: columns 2hp, 2hp+1
    const int r0 = (tid >> 6) * 8;    // 8 local rows per thread

    unsigned long long acc[8];
    float2 bv = *(const float2*)(bias + 2 * hp);
    unsigned long long bini = pack2(bv.x, bv.y);
#pragma unroll
    for (int i = 0; i < 8; i++) acc[i] = bini;

    for (int m = 0; m < NNODE; m++) {
        unsigned long long zpr = *(const unsigned long long*)&Zs[m * GH + 2 * hp];
#pragma unroll
        for (int i = 0; i < 8; i++) {
            float p = Ps[(r0 + i) * NNODE + m];
            acc[i] = fma2(pack2(p, p), zpr, acc[i]);
        }
    }

    float* yb = y + ((size_t)b * NNODE + nh) * GH;
#pragma unroll
    for (int i = 0; i < 8; i++) {
        float2 v = unpack2(acc[i]);
        *(float2*)&yb[(r0 + i) * GH + 2 * hp] = v;
    }
}

// ---------------------------------------------------------------------------
extern "C" void kernel_launch(void* const* d_in, const int* in_sizes, int n_in,
                              void* d_out, int out_size) {
    const float* x    = (const float*)d_in[0];      // (32,8,64,250) fp32
    const int*   eiw  = (const int*)d_in[1];        // (2,E) int64 or int32 words
    const float* ew   = (const float*)d_in[2];      // (E,) fp32
    const float* W    = (const float*)d_in[3];      // (128,2000) fp32
    const float* bias = (const float*)d_in[4];      // (128,) fp32
    float*       y    = (float*)d_out;              // (32,64,128) fp32

    const int E = in_sizes[1] / 2;

    gemm_build_kernel<<<129, 256>>>(x, W, eiw, ew, E);
    apply_p2_kernel<<<64, 256>>>(bias, y);
}

// round 6
// speedup vs baseline: 3.5047x; 2.0861x over previous
#include <cuda_runtime.h>
#include <cuda_bf16.h>
#include <cstdint>

// ---------------------------------------------------------------------------
// SimpleGCNNet:  Y = P^2 * X * W^T + b
//   X: (2048, 2000) fp32, W: (128, 2000), b: (128,) -> Y: (32, 64, 128)
// Kernel A (grid 161): blocks 0..159: Zp[ks] = X[m-tile 64] @ W^T over k-slice
//     of 400, bf16 hi/lo split (3 passes), warp-level mma.sync m16n8k16.
//     block 160: build P -> P2 (concurrent, uses the dynamic smem as scratch).
// Kernel B (grid 128): Y[b,:,hq] = P2 @ (sum_s Zp[s])[b,:,hq] + bias
// NOTE: all smem in kernel A is DYNAMIC (36864 B) so static+dynamic < 48 KB.
// ---------------------------------------------------------------------------

#define NNODE 64
#define GM 2048
#define GK 2000
#define GH 128
#define KSPLIT 5
#define KSLICE 400           // 25 k-tiles of 16
#define NKT 25
#define MT 64                // m rows per block
#define EPSW 1e-6f

// smem stage: bf16 planes, row stride 48 B (conflict-free ldmatrix, 16B-aligned)
//   aH @ 0 (64*48=3072), aL @ 3072, bH @ 6144 (128*48), bL @ 12288 ; stage 18432
#define STAGE_BYTES 18432
#define SMEM_DYN_BYTES (2 * STAGE_BYTES)

__device__ float g_P2[NNODE * NNODE];
__device__ float g_Zp[KSPLIT][GM * GH];

// ---- helpers --------------------------------------------------------------
__device__ __forceinline__ uint32_t smem_u32(const void* p) {
    uint32_t a;
    asm("{ .reg .u64 t; cvta.to.shared.u64 t, %1; cvt.u32.u64 %0, t; }"
        : "=r"(a) : "l"(p));
    return a;
}
__device__ __forceinline__ unsigned long long pack2(float lo, float hi) {
    unsigned long long r;
    asm("mov.b64 %0, {%1, %2};" : "=l"(r) : "f"(lo), "f"(hi));
    return r;
}
__device__ __forceinline__ unsigned long long fma2(unsigned long long a,
                                                   unsigned long long b,
                                                   unsigned long long c) {
    unsigned long long d;
    asm("fma.rn.f32x2 %0, %1, %2, %3;" : "=l"(d) : "l"(a), "l"(b), "l"(c));
    return d;
}
__device__ __forceinline__ float2 unpack2(unsigned long long v) {
    float2 f;
    asm("mov.b64 {%0, %1}, %2;" : "=f"(f.x), "=f"(f.y) : "l"(v));
    return f;
}

__device__ __forceinline__ void ldsm4(uint32_t* r, uint32_t addr) {
    asm volatile("ldmatrix.sync.aligned.m8n8.x4.shared.b16 {%0,%1,%2,%3}, [%4];"
                 : "=r"(r[0]), "=r"(r[1]), "=r"(r[2]), "=r"(r[3]) : "r"(addr));
}
__device__ __forceinline__ void mma_bf16(float* c, const uint32_t* a,
                                         uint32_t b0, uint32_t b1) {
    asm volatile(
        "mma.sync.aligned.m16n8k16.row.col.f32.bf16.bf16.f32 "
        "{%0,%1,%2,%3}, {%4,%5,%6,%7}, {%8,%9}, {%0,%1,%2,%3};"
        : "+f"(c[0]), "+f"(c[1]), "+f"(c[2]), "+f"(c[3])
        : "r"(a[0]), "r"(a[1]), "r"(a[2]), "r"(a[3]), "r"(b0), "r"(b1));
}

// fp32x4 -> bf16 hi (2 b32) + bf16 lo (2 b32)
__device__ __forceinline__ void cvt_split(float4 v, uint32_t& hp0, uint32_t& hp1,
                                          uint32_t& lp0, uint32_t& lp1) {
    asm("cvt.rn.bf16x2.f32 %0, %1, %2;" : "=r"(hp0) : "f"(v.y), "f"(v.x));
    asm("cvt.rn.bf16x2.f32 %0, %1, %2;" : "=r"(hp1) : "f"(v.w), "f"(v.z));
    float h0 = __uint_as_float(hp0 << 16);
    float h1 = __uint_as_float(hp0 & 0xFFFF0000u);
    float h2 = __uint_as_float(hp1 << 16);
    float h3 = __uint_as_float(hp1 & 0xFFFF0000u);
    asm("cvt.rn.bf16x2.f32 %0, %1, %2;" : "=r"(lp0) : "f"(v.y - h1), "f"(v.x - h0));
    asm("cvt.rn.bf16x2.f32 %0, %1, %2;" : "=r"(lp1) : "f"(v.w - h3), "f"(v.z - h2));
}
__device__ __forceinline__ void sts2(uint32_t addr, uint32_t a, uint32_t b) {
    asm volatile("st.shared.v2.b32 [%0], {%1, %2};" :: "r"(addr), "r"(a), "r"(b)
                 : "memory");
}

// ---------------------------------------------------------------------------
// build P -> P2 ; scratch lives in the kernel's DYNAMIC smem buffer
// layout: P @ 0 (16384 B), deg @ 16384, dinv @ 16640, flag @ 16896
// ---------------------------------------------------------------------------
__device__ void build_p2_body(char* dsm, const int* __restrict__ eiw,
                              const float* __restrict__ ew, int E) {
    float* P    = (float*)dsm;
    float* deg  = (float*)(dsm + 16384);
    float* dinv = (float*)(dsm + 16640);
    int*   flag = (int*)(dsm + 16896);
    const int tid = threadIdx.x;

    for (int i = tid; i < NNODE * NNODE; i += 256) P[i] = 0.0f;
    if (tid < NNODE) deg[tid] = 1.0f;   // self-loop weight 1.0
    if (tid == 0) *flag = 0;
    __syncthreads();

    // dtype detect: int64 little-endian values in [0,64) -> odd words == 0
    if (tid < 64) {
        if (eiw[2 * tid + 1] != 0) atomicOr(flag, 1);
    }
    __syncthreads();
    const bool is64 = (*flag == 0);
    const int stride = is64 ? 2 : 1;
    const int dst_base = is64 ? 2 * E : E;

    for (int e = tid; e < E; e += 256) {
        float w = ew[e];
        if (w <= 0.0f) w = EPSW;
        atomicAdd(&deg[eiw[dst_base + e * stride] & (NNODE - 1)], w);
    }
    __syncthreads();
    if (tid < NNODE) {
        float d = deg[tid];
        dinv[tid] = (d > 0.0f) ? rsqrtf(d) : 0.0f;
    }
    __syncthreads();
    for (int e = tid; e < E; e += 256) {
        float w = ew[e];
        if (w <= 0.0f) w = EPSW;
        int s = eiw[e * stride] & (NNODE - 1);
        int d = eiw[dst_base + e * stride] & (NNODE - 1);
        atomicAdd(&P[d * NNODE + s], dinv[s] * w * dinv[d]);
    }
    if (tid < NNODE) atomicAdd(&P[tid * NNODE + tid], dinv[tid] * dinv[tid]);
    __syncthreads();
    for (int i = tid; i < NNODE * NNODE; i += 256) {
        int r = i >> 6, c = i & 63;
        float acc = 0.0f;
#pragma unroll 16
        for (int m = 0; m < NNODE; m++) acc += P[r * NNODE + m] * P[m * NNODE + c];
        g_P2[i] = acc;
    }
}

// ---------------------------------------------------------------------------
// Kernel A: mma.sync bf16-split GEMM partials + P2 build
// ---------------------------------------------------------------------------
__global__ __launch_bounds__(256) void gemm_build_kernel(
    const float* __restrict__ X, const float* __restrict__ W,
    const int* __restrict__ eiw, const float* __restrict__ ew, int E) {

    extern __shared__ __align__(1024) char smem[];

    if (blockIdx.x == 160) { build_p2_body(smem, eiw, ew, E); return; }

    const uint32_t sb = smem_u32(smem);
    const int tid = threadIdx.x;
    const int wid = tid >> 5;
    const int lane = tid & 31;

    const int mt = blockIdx.x & 31;       // 0..31
    const int ks = blockIdx.x >> 5;       // 0..4
    const int m_base = mt * MT;
    const int k0 = ks * KSLICE;

    // loader roles
    const int xrow = tid >> 2, xq = (tid & 3) * 4;      // X: 64r x 16k, 1 float4
    const int brow = tid >> 1, bq = (tid & 1) * 8;      // W: 128r x 16k, 2 float4
    const float* xp = X + (size_t)(m_base + xrow) * GK + k0 + xq;
    const float* wp = W + (size_t)brow * GK + k0 + bq;

    // compute roles: 8 warps = 2(m) x 4(n); warp tile 32m x 32n
    const int warp_m = wid >> 2, warp_n = wid & 3;

    float acc[32];                        // site (f,nb): acc[(f*4+nb)*4 + ..]
#pragma unroll
    for (int i = 0; i < 32; i++) acc[i] = 0.0f;

    float4 xr, wr0, wr1;                  // prefetch regs
    xr = *(const float4*)xp;
    wr0 = *(const float4*)wp;
    wr1 = *(const float4*)(wp + 4);

    for (int t = 0; t < NKT; t++) {
        const uint32_t st = sb + (t & 1) * STAGE_BYTES;
        const uint32_t aH = st, aL = st + 3072, bH = st + 6144, bL = st + 12288;

        // ---- convert + store current tile ----
        {
            uint32_t h0, h1, l0, l1;
            cvt_split(xr, h0, h1, l0, l1);
            uint32_t off = (uint32_t)(xrow * 48 + xq * 2);
            sts2(aH + off, h0, h1);
            sts2(aL + off, l0, l1);
            cvt_split(wr0, h0, h1, l0, l1);
            off = (uint32_t)(brow * 48 + bq * 2);
            sts2(bH + off, h0, h1);
            sts2(bL + off, l0, l1);
            cvt_split(wr1, h0, h1, l0, l1);
            sts2(bH + off + 8, h0, h1);
            sts2(bL + off + 8, l0, l1);
        }
        __syncthreads();

        // ---- prefetch next tile ----
        if (t + 1 < NKT) {
            const int off = (t + 1) * 16;
            xr = *(const float4*)(xp + off);
            wr0 = *(const float4*)(wp + off);
            wr1 = *(const float4*)(wp + off + 4);
        }

        // ---- load fragments + mma ----
        uint32_t Ah[2][4], Al[2][4], Bh[2][4], Bl[2][4];
        const uint32_t lrow = (uint32_t)(lane & 15);
        const uint32_t lkh = (uint32_t)(lane >> 4) * 16;
#pragma unroll
        for (int f = 0; f < 2; f++) {
            uint32_t ra = (32 * warp_m + 16 * f + lrow) * 48 + lkh;
            ldsm4(Ah[f], aH + ra);
            ldsm4(Al[f], aL + ra);
            uint32_t rb = (32 * warp_n + 16 * f + lrow) * 48 + lkh;
            ldsm4(Bh[f], bH + rb);
            ldsm4(Bl[f], bL + rb);
        }
        // B x4 regs: {r0,r2} = n-block 2g, {r1,r3} = n-block 2g+1
#pragma unroll
        for (int f = 0; f < 2; f++) {
#pragma unroll
            for (int g = 0; g < 2; g++) {
                float* c0 = acc + (f * 4 + 2 * g) * 4;
                float* c1 = acc + (f * 4 + 2 * g + 1) * 4;
                mma_bf16(c0, Ah[f], Bh[g][0], Bh[g][2]);   // hi*hi
                mma_bf16(c1, Ah[f], Bh[g][1], Bh[g][3]);
                mma_bf16(c0, Ah[f], Bl[g][0], Bl[g][2]);   // hi*lo
                mma_bf16(c1, Ah[f], Bl[g][1], Bl[g][3]);
                mma_bf16(c0, Al[f], Bh[g][0], Bh[g][2]);   // lo*hi
                mma_bf16(c1, Al[f], Bh[g][1], Bh[g][3]);
            }
        }
        __syncthreads();
    }

    // ---- epilogue: write Z-partial ----
    float* zp = g_Zp[ks];
    const int cr = lane >> 2, cc = (lane & 3) * 2;
#pragma unroll
    for (int f = 0; f < 2; f++) {
#pragma unroll
        for (int nb = 0; nb < 4; nb++) {
            const float* c = acc + (f * 4 + nb) * 4;
            int row = m_base + 32 * warp_m + 16 * f + cr;
            int col = 32 * warp_n + 8 * nb + cc;
            *(float2*)&zp[(size_t)row * GH + col] = make_float2(c[0], c[1]);
            *(float2*)&zp[(size_t)(row + 8) * GH + col] = make_float2(c[2], c[3]);
        }
    }
}

// ---------------------------------------------------------------------------
// Kernel B: Y[b,:,hq:hq+32] = P2 @ (sum_s Zp[s])[b,:,hq:hq+32] + bias
// grid 128 = 32 batches x 4 h-quarters
// ---------------------------------------------------------------------------
__global__ __launch_bounds__(256) void apply_p2_kernel(
    const float* __restrict__ bias, float* __restrict__ y) {
    __shared__ __align__(16) float P2t[NNODE * NNODE];  // transposed [m][n]
    __shared__ __align__(16) float Zs[NNODE * 32];
    const int b = blockIdx.x >> 2;
    const int hq = (blockIdx.x & 3) * 32;
    const int tid = threadIdx.x;

    for (int i = tid; i < NNODE * NNODE; i += 256)
        P2t[(i & 63) * 64 + (i >> 6)] = g_P2[i];

    for (int p = tid; p < 512; p += 256) {
        int m = p >> 3;
        int c4 = (p & 7) * 4;
        const float* src = &g_Zp[0][((size_t)b * NNODE + m) * GH + hq + c4];
        float4 s = *(const float4*)src;
#pragma unroll
        for (int si = 1; si < KSPLIT; si++) {
            float4 v = *(const float4*)(src + (size_t)si * GM * GH);
            s.x += v.x; s.y += v.y; s.z += v.z; s.w += v.w;
        }
        *(float4*)&Zs[m * 32 + c4] = s;
    }
    __syncthreads();

    const int hp = tid & 15;
    const int n0 = (tid >> 4) * 4;

    unsigned long long acc[4];
    float2 bv = *(const float2*)(bias + hq + 2 * hp);
    unsigned long long bini = pack2(bv.x, bv.y);
#pragma unroll
    for (int j = 0; j < 4; j++) acc[j] = bini;

#pragma unroll 8
    for (int m = 0; m < NNODE; m++) {
        unsigned long long z = *(const unsigned long long*)&Zs[m * 32 + 2 * hp];
        float4 p4 = *(const float4*)&P2t[m * 64 + n0];
        acc[0] = fma2(pack2(p4.x, p4.x), z, acc[0]);
        acc[1] = fma2(pack2(p4.y, p4.y), z, acc[1]);
        acc[2] = fma2(pack2(p4.z, p4.z), z, acc[2]);
        acc[3] = fma2(pack2(p4.w, p4.w), z, acc[3]);
    }

    float* yb = y + ((size_t)b * NNODE + n0) * GH + hq + 2 * hp;
#pragma unroll
    for (int j = 0; j < 4; j++) {
        float2 v = unpack2(acc[j]);
        *(float2*)(yb + (size_t)j * GH) = v;
    }
}

// ---------------------------------------------------------------------------
extern "C" void kernel_launch(void* const* d_in, const int* in_sizes, int n_in,
                              void* d_out, int out_size) {
    const float* x    = (const float*)d_in[0];
    const int*   eiw  = (const int*)d_in[1];
    const float* ew   = (const float*)d_in[2];
    const float* W    = (const float*)d_in[3];
    const float* bias = (const float*)d_in[4];
    float*       y    = (float*)d_out;

    const int E = in_sizes[1] / 2;

    gemm_build_kernel<<<161, 256, SMEM_DYN_BYTES>>>(x, W, eiw, ew, E);
    apply_p2_kernel<<<128, 256>>>(bias, y);
}

// round 7
// speedup vs baseline: 3.7237x; 1.0625x over previous
#include <cuda_runtime.h>
#include <cuda_fp16.h>
#include <cstdint>

// ---------------------------------------------------------------------------
// SimpleGCNNet:  Y = P^2 * X * W^T + b
//   X: (2048, 2000) fp32, W: (128, 2000), b: (128,) -> Y: (32, 64, 128)
// Kernel A (grid 161): blocks 0..159: Zp[ks] = X[m-tile 64] @ W^T over k-slice
//     of 400, SINGLE-PASS fp16 mma.sync m16n8k16 (error ~2e-4 << 1e-3).
//     block 160: build P -> P2 (+ transposed copy), in dynamic smem scratch.
// Kernel B (grid 256): Y[b,:,hs:hs+16] = P2 @ (sum_s Zp[s])[b,:,hs:hs+16] + bias
// ---------------------------------------------------------------------------

#define NNODE 64
#define GM 2048
#define GK 2000
#define GH 128
#define KSPLIT 5
#define KSLICE 400           // 25 k-tiles of 16
#define NKT 25
#define MT 64
#define EPSW 1e-6f

// smem stage: fp16 planes, row stride 48 B (conflict-free ldmatrix)
//   aH @ 0 (64*48=3072), bH @ 3072 (128*48=6144) ; stage 9216, x2 = 18432
#define STAGE_BYTES 9216
#define SMEM_DYN_BYTES (2 * STAGE_BYTES)

__device__ float g_P2t[NNODE * NNODE];    // transposed: [m][n]
__device__ float g_Zp[KSPLIT][GM * GH];

// ---- helpers --------------------------------------------------------------
__device__ __forceinline__ uint32_t smem_u32(const void* p) {
    uint32_t a;
    asm("{ .reg .u64 t; cvta.to.shared.u64 t, %1; cvt.u32.u64 %0, t; }"
        : "=r"(a) : "l"(p));
    return a;
}
__device__ __forceinline__ unsigned long long pack2(float lo, float hi) {
    unsigned long long r;
    asm("mov.b64 %0, {%1, %2};" : "=l"(r) : "f"(lo), "f"(hi));
    return r;
}
__device__ __forceinline__ unsigned long long fma2(unsigned long long a,
                                                   unsigned long long b,
                                                   unsigned long long c) {
    unsigned long long d;
    asm("fma.rn.f32x2 %0, %1, %2, %3;" : "=l"(d) : "l"(a), "l"(b), "l"(c));
    return d;
}
__device__ __forceinline__ float2 unpack2(unsigned long long v) {
    float2 f;
    asm("mov.b64 {%0, %1}, %2;" : "=f"(f.x), "=f"(f.y) : "l"(v));
    return f;
}
__device__ __forceinline__ void ldsm4(uint32_t* r, uint32_t addr) {
    asm volatile("ldmatrix.sync.aligned.m8n8.x4.shared.b16 {%0,%1,%2,%3}, [%4];"
                 : "=r"(r[0]), "=r"(r[1]), "=r"(r[2]), "=r"(r[3]) : "r"(addr));
}
__device__ __forceinline__ void mma_f16(float* c, const uint32_t* a,
                                        uint32_t b0, uint32_t b1) {
    asm volatile(
        "mma.sync.aligned.m16n8k16.row.col.f32.f16.f16.f32 "
        "{%0,%1,%2,%3}, {%4,%5,%6,%7}, {%8,%9}, {%0,%1,%2,%3};"
        : "+f"(c[0]), "+f"(c[1]), "+f"(c[2]), "+f"(c[3])
        : "r"(a[0]), "r"(a[1]), "r"(a[2]), "r"(a[3]), "r"(b0), "r"(b1));
}
// fp32x4 -> 2x packed fp16x2 (lo half = .x/.z, hi half = .y/.w)
__device__ __forceinline__ void cvt_h2(float4 v, uint32_t& h0, uint32_t& h1) {
    asm("cvt.rn.f16x2.f32 %0, %1, %2;" : "=r"(h0) : "f"(v.y), "f"(v.x));
    asm("cvt.rn.f16x2.f32 %0, %1, %2;" : "=r"(h1) : "f"(v.w), "f"(v.z));
}
__device__ __forceinline__ void sts2(uint32_t addr, uint32_t a, uint32_t b) {
    asm volatile("st.shared.v2.b32 [%0], {%1, %2};" :: "r"(addr), "r"(a), "r"(b)
                 : "memory");
}

// ---------------------------------------------------------------------------
// build P -> P2 (+ transposed), scratch in dynamic smem
// layout: P @ 0 (16384), deg @ 16384, dinv @ 16640, flag @ 16896
// ---------------------------------------------------------------------------
__device__ void build_p2_body(char* dsm, const int* __restrict__ eiw,
                              const float* __restrict__ ew, int E) {
    float* P    = (float*)dsm;
    float* deg  = (float*)(dsm + 16384);
    float* dinv = (float*)(dsm + 16640);
    int*   flag = (int*)(dsm + 16896);
    const int tid = threadIdx.x;

    for (int i = tid; i < NNODE * NNODE; i += 256) P[i] = 0.0f;
    if (tid < NNODE) deg[tid] = 1.0f;   // self-loop weight 1.0
    if (tid == 0) *flag = 0;
    __syncthreads();

    // dtype detect: int64 little-endian values in [0,64) -> odd words == 0
    if (tid < 64) {
        if (eiw[2 * tid + 1] != 0) atomicOr(flag, 1);
    }
    __syncthreads();
    const bool is64 = (*flag == 0);
    const int stride = is64 ? 2 : 1;
    const int dst_base = is64 ? 2 * E : E;

    for (int e = tid; e < E; e += 256) {
        float w = ew[e];
        if (w <= 0.0f) w = EPSW;
        atomicAdd(&deg[eiw[dst_base + e * stride] & (NNODE - 1)], w);
    }
    __syncthreads();
    if (tid < NNODE) {
        float d = deg[tid];
        dinv[tid] = (d > 0.0f) ? rsqrtf(d) : 0.0f;
    }
    __syncthreads();
    for (int e = tid; e < E; e += 256) {
        float w = ew[e];
        if (w <= 0.0f) w = EPSW;
        int s = eiw[e * stride] & (NNODE - 1);
        int d = eiw[dst_base + e * stride] & (NNODE - 1);
        atomicAdd(&P[d * NNODE + s], dinv[s] * w * dinv[d]);
    }
    if (tid < NNODE) atomicAdd(&P[tid * NNODE + tid], dinv[tid] * dinv[tid]);
    __syncthreads();
    for (int i = tid; i < NNODE * NNODE; i += 256) {
        int r = i >> 6, c = i & 63;
        float acc = 0.0f;
#pragma unroll 16
        for (int m = 0; m < NNODE; m++) acc += P[r * NNODE + m] * P[m * NNODE + c];
        g_P2t[c * NNODE + r] = acc;     // store transposed: [m][n]
    }
}

// ---------------------------------------------------------------------------
// Kernel A: single-pass fp16 mma GEMM partials + P2 build
// ---------------------------------------------------------------------------
__global__ __launch_bounds__(256) void gemm_build_kernel(
    const float* __restrict__ X, const float* __restrict__ W,
    const int* __restrict__ eiw, const float* __restrict__ ew, int E) {

    extern __shared__ __align__(1024) char smem[];

    if (blockIdx.x == 160) { build_p2_body(smem, eiw, ew, E); return; }

    const uint32_t sb = smem_u32(smem);
    const int tid = threadIdx.x;
    const int wid = tid >> 5;
    const int lane = tid & 31;

    const int mt = blockIdx.x & 31;       // 0..31
    const int ks = blockIdx.x >> 5;       // 0..4
    const int m_base = mt * MT;
    const int k0 = ks * KSLICE;

    // loader roles
    const int xrow = tid >> 2, xq = (tid & 3) * 4;      // X: 64r x 16k, 1 float4
    const int brow = tid >> 1, bq = (tid & 1) * 8;      // W: 128r x 16k, 2 float4
    const float* xp = X + (size_t)(m_base + xrow) * GK + k0 + xq;
    const float* wp = W + (size_t)brow * GK + k0 + bq;
    const uint32_t xoff = (uint32_t)(xrow * 48 + xq * 2);
    const uint32_t boff = (uint32_t)(brow * 48 + bq * 2);

    // compute roles: 8 warps = 2(m) x 4(n); warp tile 32m x 32n
    const int warp_m = wid >> 2, warp_n = wid & 3;

    float acc[32];
#pragma unroll
    for (int i = 0; i < 32; i++) acc[i] = 0.0f;

    // prologue: store tile 0 into buf0; prefetch tile 1 into regs
    {
        float4 xv = *(const float4*)xp;
        float4 w0 = *(const float4*)wp;
        float4 w1 = *(const float4*)(wp + 4);
        uint32_t h0, h1;
        cvt_h2(xv, h0, h1); sts2(sb + xoff, h0, h1);
        cvt_h2(w0, h0, h1); sts2(sb + 3072 + boff, h0, h1);
        cvt_h2(w1, h0, h1); sts2(sb + 3072 + boff + 8, h0, h1);
    }
    float4 xr = *(const float4*)(xp + 16);
    float4 wr0 = *(const float4*)(wp + 16);
    float4 wr1 = *(const float4*)(wp + 20);
    __syncthreads();

    const uint32_t lrow = (uint32_t)(lane & 15);
    const uint32_t lkh = (uint32_t)(lane >> 4) * 16;
    const uint32_t raBase = (32u * warp_m + lrow) * 48 + lkh;
    const uint32_t rbBase = (32u * warp_n + lrow) * 48 + lkh;

    for (int t = 0; t < NKT; t++) {
        const uint32_t st = sb + (t & 1) * STAGE_BYTES;

        // ---- load fragments from current buffer ----
        uint32_t Ah[2][4], Bh[2][4];
#pragma unroll
        for (int f = 0; f < 2; f++) {
            ldsm4(Ah[f], st + raBase + 16u * 48u * f);
            ldsm4(Bh[f], st + 3072 + rbBase + 16u * 48u * f);
        }

        // ---- store tile t+1 (in regs) into the other buffer ----
        if (t + 1 < NKT) {
            const uint32_t so = sb + ((t + 1) & 1) * STAGE_BYTES;
            uint32_t h0, h1;
            cvt_h2(xr, h0, h1);  sts2(so + xoff, h0, h1);
            cvt_h2(wr0, h0, h1); sts2(so + 3072 + boff, h0, h1);
            cvt_h2(wr1, h0, h1); sts2(so + 3072 + boff + 8, h0, h1);
        }
        // ---- prefetch tile t+2 ----
        if (t + 2 < NKT) {
            const int off = (t + 2) * 16;
            xr = *(const float4*)(xp + off);
            wr0 = *(const float4*)(wp + off);
            wr1 = *(const float4*)(wp + off + 4);
        }
        __syncthreads();

        // ---- mma (8 per warp) ----
#pragma unroll
        for (int f = 0; f < 2; f++) {
#pragma unroll
            for (int g = 0; g < 2; g++) {
                float* c0 = acc + (f * 4 + 2 * g) * 4;
                float* c1 = acc + (f * 4 + 2 * g + 1) * 4;
                mma_f16(c0, Ah[f], Bh[g][0], Bh[g][2]);
                mma_f16(c1, Ah[f], Bh[g][1], Bh[g][3]);
            }
        }
    }

    // ---- epilogue: write Z-partial ----
    float* zp = g_Zp[ks];
    const int cr = lane >> 2, cc = (lane & 3) * 2;
#pragma unroll
    for (int f = 0; f < 2; f++) {
#pragma unroll
        for (int nb = 0; nb < 4; nb++) {
            const float* c = acc + (f * 4 + nb) * 4;
            int row = m_base + 32 * warp_m + 16 * f + cr;
            int col = 32 * warp_n + 8 * nb + cc;
            *(float2*)&zp[(size_t)row * GH + col] = make_float2(c[0], c[1]);
            *(float2*)&zp[(size_t)(row + 8) * GH + col] = make_float2(c[2], c[3]);
        }
    }
}

// ---------------------------------------------------------------------------
// Kernel B: Y[b,:,hs:hs+16] = P2 @ (sum_s Zp[s])[b,:,hs:hs+16] + bias
// grid 256 = 32 batches x 8 h-slices of 16
// ---------------------------------------------------------------------------
__global__ __launch_bounds__(256) void apply_p2_kernel(
    const float* __restrict__ bias, float* __restrict__ y) {
    __shared__ __align__(16) float P2t[NNODE * NNODE];  // [m][n], 16 KB
    __shared__ __align__(16) float Zs[NNODE * 16];      // [m][hc], 4 KB
    const int b = blockIdx.x >> 3;
    const int hs = (blockIdx.x & 7) * 16;
    const int tid = threadIdx.x;

    // coalesced load of pre-transposed P2
    for (int i = tid; i < NNODE * NNODE; i += 256)
        P2t[i] = g_P2t[i];

    // sum 5 Z-partials: 64 rows x 16 cols = 256 float4s, one per thread
    {
        int m = tid >> 2;
        int c4 = (tid & 3) * 4;
        const float* src = &g_Zp[0][((size_t)b * NNODE + m) * GH + hs + c4];
        float4 s = *(const float4*)src;
#pragma unroll
        for (int si = 1; si < KSPLIT; si++) {
            float4 v = *(const float4*)(src + (size_t)si * GM * GH);
            s.x += v.x; s.y += v.y; s.z += v.z; s.w += v.w;
        }
        *(float4*)&Zs[m * 16 + c4] = s;
    }
    __syncthreads();

    const int hp = tid & 7;           // h-pair within slice
    const int n0 = (tid >> 3) * 2;    // 2 output rows

    unsigned long long acc0, acc1;
    float2 bv = *(const float2*)(bias + hs + 2 * hp);
    acc0 = acc1 = pack2(bv.x, bv.y);

#pragma unroll 8
    for (int m = 0; m < NNODE; m++) {
        unsigned long long z = *(const unsigned long long*)&Zs[m * 16 + 2 * hp];
        float2 p = *(const float2*)&P2t[m * 64 + n0];
        acc0 = fma2(pack2(p.x, p.x), z, acc0);
        acc1 = fma2(pack2(p.y, p.y), z, acc1);
    }

    float* yb = y + ((size_t)b * NNODE + n0) * GH + hs + 2 * hp;
    float2 v0 = unpack2(acc0), v1 = unpack2(acc1);
    *(float2*)yb = v0;
    *(float2*)(yb + GH) = v1;
}

// ---------------------------------------------------------------------------
extern "C" void kernel_launch(void* const* d_in, const int* in_sizes, int n_in,
                              void* d_out, int out_size) {
    const float* x    = (const float*)d_in[0];
    const int*   eiw  = (const int*)d_in[1];
    const float* ew   = (const float*)d_in[2];
    const float* W    = (const float*)d_in[3];
    const float* bias = (const float*)d_in[4];
    float*       y    = (float*)d_out;

    const int E = in_sizes[1] / 2;

    gemm_build_kernel<<<161, 256, SMEM_DYN_BYTES>>>(x, W, eiw, ew, E);
    apply_p2_kernel<<<256, 256>>>(bias, y);
}